// round 3
// baseline (speedup 1.0000x reference)
#include <cuda_runtime.h>
#include <cuda_pipeline.h>
#include <math.h>

#define BATCH 16
#define NN    2048
#define KH    12
#define FD    128
#define OD    64

// attention scratch: att[2][NN][6][6]
__device__ float g_att[2 * NN * 36];

// ---------------------------------------------------------------------------
// Kernel A: attention matrices. One warp per (i, n).
// ---------------------------------------------------------------------------
__global__ void __launch_bounds__(256) attn_scores_kernel(
    const float* __restrict__ h, const int* __restrict__ adj,
    const float* __restrict__ W, const float* __restrict__ a)
{
    __shared__ float wa1[FD], wa2[FD];
    const int t = threadIdx.x;
    const int i = blockIdx.x >> 8;

    if (t < FD) {
        float r1 = 0.f, r2 = 0.f;
        const float* wr = W + t * OD;
        const float* ap = a + i * 2 * OD;
        #pragma unroll 16
        for (int o = 0; o < OD; ++o) {
            const float w = wr[o];
            r1 = fmaf(w, ap[o], r1);
            r2 = fmaf(w, ap[OD + o], r2);
        }
        wa1[t] = r1; wa2[t] = r2;
    }
    __syncthreads();

    const int wid = t >> 5, l = t & 31;
    const int n = ((blockIdx.x & 255) << 3) + wid;

    float p1[6], p2[6];
    const float* hb = h + (((size_t)i * NN + n) * KH + i * 6) * FD;
    #pragma unroll
    for (int q = 0; q < 6; ++q) { p1[q] = 0.f; p2[q] = 0.f; }
    #pragma unroll
    for (int it = 0; it < 4; ++it) {
        const int f = l + it * 32;
        const float w1 = wa1[f], w2 = wa2[f];
        #pragma unroll
        for (int q = 0; q < 6; ++q) {
            const float hv = hb[q * FD + f];
            p1[q] = fmaf(hv, w1, p1[q]);
            p2[q] = fmaf(hv, w2, p2[q]);
        }
    }
    #pragma unroll
    for (int off = 16; off > 0; off >>= 1) {
        #pragma unroll
        for (int q = 0; q < 6; ++q) {
            p1[q] += __shfl_xor_sync(0xffffffffu, p1[q], off);
            p2[q] += __shfl_xor_sync(0xffffffffu, p2[q], off);
        }
    }

    if (l < 6) {
        const int p = l;
        float e[6];
        float m = -1e30f;
        #pragma unroll
        for (int q = 0; q < 6; ++q) {
            float v = p1[p] + p2[q];
            v = v > 0.f ? v : 0.2f * v;
            if (adj[i * 36 + p * 6 + q] <= 0) v = -9.0e15f;
            e[q] = v;
            m = fmaxf(m, v);
        }
        float sum = 0.f;
        #pragma unroll
        for (int q = 0; q < 6; ++q) { e[q] = expf(e[q] - m); sum += e[q]; }
        const float inv = 1.f / sum;
        float* dst = g_att + ((size_t)i * NN + n) * 36 + p * 6;
        #pragma unroll
        for (int q = 0; q < 6; ++q) dst[q] = e[q] * inv;
    }
}

// ---------------------------------------------------------------------------
// Kernel B: out = elu( postmix( h @ W ) )
// 256 threads / block. Warp w -> (slice sl = w>>1, group g = w&1).
// Lane: cg = lane&15 (4 output cols), qh = lane>>4 (q-rows qh*3..qh*3+2).
// Each thread: Wh[3 rows][4 cols] in f32x2 accumulators. Postmix mixes the
// 6x6 attention in registers with one shfl_xor(16) exchange between halves.
// ---------------------------------------------------------------------------

#define NSL     4
#define PHASES  4
#define NT      (NSL * PHASES)
#define THREADS 256

#define SM_W    0                              // 8192 floats
#define SM_ASR  8192                           // 2 * NSL*12*128 = 12288
#define SM_ATT  (SM_ASR + 2 * NSL * KH * FD)   // 2 * NSL*72 = 576
#define SM_TOT  (SM_ATT + 2 * NSL * 72)

typedef unsigned long long u64;

__device__ __forceinline__ u64 splat2(float x) {
    u64 d;
    asm("mov.b64 %0, {%1, %1};" : "=l"(d) : "f"(x));
    return d;
}
__device__ __forceinline__ void fma2(u64& acc, u64 a, u64 b) {
    asm("fma.rn.f32x2 %0, %1, %2, %0;" : "+l"(acc) : "l"(a), "l"(b));
}
__device__ __forceinline__ u64 add2(u64 a, u64 b) {
    u64 d;
    asm("add.rn.f32x2 %0, %1, %2;" : "=l"(d) : "l"(a), "l"(b));
    return d;
}

__global__ void __launch_bounds__(THREADS, 2) gat_main_kernel(
    const float* __restrict__ h, const float* __restrict__ W,
    float* __restrict__ out)
{
    extern __shared__ float sm[];
    float* Wsm  = sm + SM_W;
    float* Asr  = sm + SM_ASR;
    float* attb = sm + SM_ATT;

    const int t  = threadIdx.x;
    const int b  = blockIdx.y;
    const int n0 = blockIdx.x * NT;

    auto load_phase = [&](int phn, int buf) {
        const int nbase = n0 + phn * NSL;
        float4* dst = (float4*)(Asr + buf * (NSL * KH * FD));
        for (int idx = t; idx < NSL * 384; idx += THREADS) {   // 1536 float4
            const int slc = idx / 384;
            const int r   = idx - slc * 384;
            __pipeline_memcpy_async(
                dst + idx,
                (const float4*)h + ((size_t)(b * NN + nbase + slc)) * 384 + r, 16);
        }
        for (int idx = t; idx < NSL * 72; idx += THREADS) {
            const int slc = idx / 72;
            const int j   = idx - slc * 72;
            const int gi  = j / 36;
            const int s   = j - gi * 36;
            __pipeline_memcpy_async(
                attb + buf * (NSL * 72) + idx,
                g_att + ((size_t)gi * NN + nbase + slc) * 36 + s, 4);
        }
    };

    for (int idx = t; idx < 2048; idx += THREADS)
        __pipeline_memcpy_async((float4*)Wsm + idx, (const float4*)W + idx, 16);
    load_phase(0, 0);
    __pipeline_commit();
    __pipeline_wait_prior(0);
    __syncthreads();

    const int w    = t >> 5;
    const int sl   = w >> 1;          // slice 0..3
    const int g    = w & 1;           // k-group 0/1
    const int lane = t & 31;
    const int cg   = lane & 15;       // output cols cg*4..cg*4+3
    const int qh   = lane >> 4;       // q-half: rows qh*3..qh*3+2

    for (int ph = 0; ph < PHASES; ++ph) {
        const int buf = ph & 1;

        if (ph + 1 < PHASES) {
            load_phase(ph + 1, buf ^ 1);
            __pipeline_commit();
        }

        const float* Ab = Asr + buf * (NSL * KH * FD)
                        + (sl * KH + g * 6 + qh * 3) * FD;

        u64 acc[3][2];
        #pragma unroll
        for (int q = 0; q < 3; ++q) { acc[q][0] = 0ull; acc[q][1] = 0ull; }

        #pragma unroll 4
        for (int f4 = 0; f4 < 32; ++f4) {
            float4 a4[3];
            #pragma unroll
            for (int q = 0; q < 3; ++q)
                a4[q] = ((const float4*)(Ab + q * FD))[f4];
            #pragma unroll
            for (int j = 0; j < 4; ++j) {
                const ulonglong2 wv =
                    *(const ulonglong2*)(Wsm + (f4 * 4 + j) * OD + cg * 4);
                #pragma unroll
                for (int q = 0; q < 3; ++q) {
                    const float av = (j == 0) ? a4[q].x : (j == 1) ? a4[q].y :
                                     (j == 2) ? a4[q].z : a4[q].w;
                    const u64 d = splat2(av);
                    fma2(acc[q][0], d, wv.x);
                    fma2(acc[q][1], d, wv.y);
                }
            }
        }

        // ---- register post-mix: out[p] = sum_q att[p][q] * Wh[q] ----
        // This lane holds q = qh*3..qh*3+2. Compute partials for own p-half
        // and the other p-half; exchange the latter with the partner lane.
        const int n = n0 + ph * NSL + sl;
        const float* at = attb + buf * (NSL * 72) + sl * 72 + g * 36;

        u64 own[3][2], oth[3][2];
        #pragma unroll
        for (int pl = 0; pl < 3; ++pl) {
            own[pl][0] = own[pl][1] = 0ull;
            oth[pl][0] = oth[pl][1] = 0ull;
            const int p_own = qh * 3 + pl;
            const int p_oth = (1 - qh) * 3 + pl;
            #pragma unroll
            for (int q = 0; q < 3; ++q) {
                const int qg = qh * 3 + q;
                const u64 d1 = splat2(at[p_own * 6 + qg]);
                fma2(own[pl][0], d1, acc[q][0]);
                fma2(own[pl][1], d1, acc[q][1]);
                const u64 d2 = splat2(at[p_oth * 6 + qg]);
                fma2(oth[pl][0], d2, acc[q][0]);
                fma2(oth[pl][1], d2, acc[q][1]);
            }
        }

        #pragma unroll
        for (int pl = 0; pl < 3; ++pl) {
            const u64 r0 = add2(own[pl][0],
                                __shfl_xor_sync(0xffffffffu, oth[pl][0], 16));
            const u64 r1 = add2(own[pl][1],
                                __shfl_xor_sync(0xffffffffu, oth[pl][1], 16));
            const float2 v01 = *(const float2*)(&r0);
            const float2 v23 = *(const float2*)(&r1);
            float4 o4;
            o4.x = v01.x > 0.f ? v01.x : expm1f(v01.x);
            o4.y = v01.y > 0.f ? v01.y : expm1f(v01.y);
            o4.z = v23.x > 0.f ? v23.x : expm1f(v23.x);
            o4.w = v23.y > 0.f ? v23.y : expm1f(v23.y);
            const int p = g * 6 + qh * 3 + pl;
            *(float4*)(out + (((size_t)b * NN + n) * KH + p) * OD + cg * 4) = o4;
        }

        __pipeline_wait_prior(0);
        __syncthreads();
    }
}

// ---------------------------------------------------------------------------
extern "C" void kernel_launch(void* const* d_in, const int* in_sizes, int n_in,
                              void* d_out, int out_size)
{
    (void)in_sizes; (void)n_in; (void)out_size;
    const float* h   = (const float*)d_in[0];
    const int*   adj = (const int*)d_in[1];
    const float* W   = (const float*)d_in[2];
    const float* a   = (const float*)d_in[3];
    float* out = (float*)d_out;

    attn_scores_kernel<<<512, 256>>>(h, adj, W, a);

    cudaFuncSetAttribute(gat_main_kernel,
                         cudaFuncAttributeMaxDynamicSharedMemorySize,
                         SM_TOT * (int)sizeof(float));
    gat_main_kernel<<<dim3(NN / NT, BATCH), THREADS, SM_TOT * sizeof(float)>>>(
        h, W, out);
}